// round 14
// baseline (speedup 1.0000x reference)
#include <cuda_runtime.h>
#include <cstdint>
#include <math.h>

// Problem constants
#define TT 512
#define BB 8
#define DD 512
#define NN 64

// Scratch (allocation-free rule: __device__ globals)
__device__ float g_k[TT * BB * DD];
__device__ float g_q[TT * BB * DD];
__device__ float g_wx[TT * BB * NN];     // W_x @ x + b
__device__ float g_alpha[TT * BB * NN];  // sigmoid(W_alpha @ x + b_alpha)

// ---------------------------------------------------------------------------
// Fast tanh: tanh(x) = 1 - 2/(1 + e^{2x})  (MUFU ex2 + rcp; abs err ~1e-7)
// ---------------------------------------------------------------------------
__device__ __forceinline__ float fast_tanh(float x) {
    float e;
    asm("ex2.approx.f32 %0, %1;" : "=f"(e) : "f"(x * 2.8853900817779268f));
    float r;
    asm("rcp.approx.f32 %0, %1;" : "=f"(r) : "f"(e + 1.0f));
    return fmaf(-2.0f, r, 1.0f);
}
__device__ __forceinline__ float warp_sum(float v) {
    v += __shfl_xor_sync(0xffffffffu, v, 16);
    v += __shfl_xor_sync(0xffffffffu, v, 8);
    v += __shfl_xor_sync(0xffffffffu, v, 4);
    v += __shfl_xor_sync(0xffffffffu, v, 2);
    v += __shfl_xor_sync(0xffffffffu, v, 1);
    return v;
}
__device__ __forceinline__ float dot4(const float4 a, const float4 b) {
    return fmaf(a.x, b.x, fmaf(a.y, b.y, fmaf(a.z, b.z, a.w * b.w)));
}

// ============================================================================
// Kernel 1: fused projection GEMM (unchanged — passing, ~116us)
// ============================================================================
#define PM 4096
#define PK 512
#define PN 1152
#define TBM 128
#define TBN 128
#define TBK 16

__global__ __launch_bounds__(256) void proj_kernel(
    const float* __restrict__ x,
    const float* __restrict__ Wk, const float* __restrict__ Wq,
    const float* __restrict__ Wx, const float* __restrict__ Wa,
    const float* __restrict__ bvec, const float* __restrict__ ba)
{
    __shared__ float As[TBK][TBM + 4];
    __shared__ float Bs[TBK][TBN + 4];

    const int tid = threadIdx.x;
    const int tx = tid & 15;
    const int ty = tid >> 4;
    const int m0 = blockIdx.x * TBM;
    const int n0 = blockIdx.y * TBN;

    const int kq = tid & 3;
    const int r0 = tid >> 2;

    const float* wr0p;
    const float* wr1p;
    {
        int jg = n0 + r0;
        wr0p = (jg < 512) ? Wk + (size_t)jg * 512
             : (jg < 1024) ? Wq + (size_t)(jg - 512) * 512
             : (jg < 1088) ? Wx + (size_t)(jg - 1024) * 512
                           : Wa + (size_t)(jg - 1088) * 512;
        jg = n0 + r0 + 64;
        wr1p = (jg < 512) ? Wk + (size_t)jg * 512
             : (jg < 1024) ? Wq + (size_t)(jg - 512) * 512
             : (jg < 1088) ? Wx + (size_t)(jg - 1024) * 512
                           : Wa + (size_t)(jg - 1088) * 512;
    }
    const float* xr0 = x + (size_t)(m0 + r0) * PK;
    const float* xr1 = x + (size_t)(m0 + r0 + 64) * PK;

    float acc[8][8];
#pragma unroll
    for (int i = 0; i < 8; i++)
#pragma unroll
        for (int j = 0; j < 8; j++) acc[i][j] = 0.0f;

    for (int kt = 0; kt < PK; kt += TBK) {
        float4 a0 = *(const float4*)(xr0 + kt + kq * 4);
        float4 a1 = *(const float4*)(xr1 + kt + kq * 4);
        float4 b0 = *(const float4*)(wr0p + kt + kq * 4);
        float4 b1 = *(const float4*)(wr1p + kt + kq * 4);

        As[kq * 4 + 0][r0] = a0.x; As[kq * 4 + 1][r0] = a0.y;
        As[kq * 4 + 2][r0] = a0.z; As[kq * 4 + 3][r0] = a0.w;
        As[kq * 4 + 0][r0 + 64] = a1.x; As[kq * 4 + 1][r0 + 64] = a1.y;
        As[kq * 4 + 2][r0 + 64] = a1.z; As[kq * 4 + 3][r0 + 64] = a1.w;

        Bs[kq * 4 + 0][r0] = b0.x; Bs[kq * 4 + 1][r0] = b0.y;
        Bs[kq * 4 + 2][r0] = b0.z; Bs[kq * 4 + 3][r0] = b0.w;
        Bs[kq * 4 + 0][r0 + 64] = b1.x; Bs[kq * 4 + 1][r0 + 64] = b1.y;
        Bs[kq * 4 + 2][r0 + 64] = b1.z; Bs[kq * 4 + 3][r0 + 64] = b1.w;

        __syncthreads();

#pragma unroll
        for (int kk = 0; kk < TBK; kk++) {
            float a[8], bq[8];
            *(float4*)&a[0]  = *(const float4*)&As[kk][ty * 8];
            *(float4*)&a[4]  = *(const float4*)&As[kk][ty * 8 + 4];
            *(float4*)&bq[0] = *(const float4*)&Bs[kk][tx * 8];
            *(float4*)&bq[4] = *(const float4*)&Bs[kk][tx * 8 + 4];
#pragma unroll
            for (int i = 0; i < 8; i++)
#pragma unroll
                for (int j = 0; j < 8; j++)
                    acc[i][j] = fmaf(a[i], bq[j], acc[i][j]);
        }
        __syncthreads();
    }

    const int c0 = n0 + tx * 8;
    if (c0 < 512) {
#pragma unroll
        for (int i = 0; i < 8; i++) {
            int r = m0 + ty * 8 + i;
            float* base = g_k + (size_t)r * DD + c0;
            *(float4*)(base)     = make_float4(acc[i][0], acc[i][1], acc[i][2], acc[i][3]);
            *(float4*)(base + 4) = make_float4(acc[i][4], acc[i][5], acc[i][6], acc[i][7]);
        }
    } else if (c0 < 1024) {
#pragma unroll
        for (int i = 0; i < 8; i++) {
            int r = m0 + ty * 8 + i;
            float* base = g_q + (size_t)r * DD + (c0 - 512);
            *(float4*)(base)     = make_float4(acc[i][0], acc[i][1], acc[i][2], acc[i][3]);
            *(float4*)(base + 4) = make_float4(acc[i][4], acc[i][5], acc[i][6], acc[i][7]);
        }
    } else if (c0 < 1088) {
        const int cc = c0 - 1024;
        float bb[8];
#pragma unroll
        for (int j = 0; j < 8; j++) bb[j] = bvec[cc + j];
#pragma unroll
        for (int i = 0; i < 8; i++) {
            int r = m0 + ty * 8 + i;
            float* base = g_wx + (size_t)r * NN + cc;
#pragma unroll
            for (int j = 0; j < 8; j++) base[j] = acc[i][j] + bb[j];
        }
    } else {
        const int cc = c0 - 1088;
        float bb[8];
#pragma unroll
        for (int j = 0; j < 8; j++) bb[j] = ba[cc + j];
#pragma unroll
        for (int i = 0; i < 8; i++) {
            int r = m0 + ty * 8 + i;
            float* base = g_alpha + (size_t)r * NN + cc;
#pragma unroll
            for (int j = 0; j < 8; j++)
                base[j] = 1.0f / (1.0f + expf(-(acc[i][j] + bb[j])));
        }
    }
}

// ============================================================================
// Kernel 2: serial recurrence, 8-CTA cluster per batch (R11 layout).
// Exchange v3: producers write (r, stamp=t+1) as ONE 8-byte st.shared::cluster
// into every CTA's slot table; consumers spin on a local volatile 16B LDS
// until both stamps match. No mbarrier, no bulk copy, no fences.
// Slot reuse at distance 2 is ordered by the warp-sync participation chain.
// ============================================================================
#define UPD4(s, k) do { \
    s.x = fmaf(al, s.x, c2 * k.x); \
    s.y = fmaf(al, s.y, c2 * k.y); \
    s.z = fmaf(al, s.z, c2 * k.z); \
    s.w = fmaf(al, s.w, c2 * k.w); } while (0)

__global__ void __cluster_dims__(8, 1, 1) __launch_bounds__(256, 1)
recur_kernel(const float* __restrict__ S0, const float* __restrict__ Wr,
             float* __restrict__ out)
{
    const int b    = blockIdx.x >> 3;
    const int rank = blockIdx.x & 7;
    const int w    = threadIdx.x >> 5;
    const int lane = threadIdx.x & 31;
    const int n    = rank * 8 + w;

    // rslot[ib][n] = { float r; uint32 stamp; }  (8B, written atomically)
    __shared__ __align__(16) uint64_t rslot[2][NN];

    const uint32_t rs_local = (uint32_t)__cvta_generic_to_shared(&rslot[0][0]);

    // zero stamps
    if (threadIdx.x < 2 * NN) rslot[threadIdx.x >> 6][threadIdx.x & 63] = 0ull;
    __syncthreads();
    asm volatile("barrier.cluster.arrive.aligned;" ::: "memory");
    asm volatile("barrier.cluster.wait.aligned;"   ::: "memory");

    // Producer push address: lanes 0-7 target CTA 'lane', slot n
    uint32_t dst_slot = 0;
    if (lane < 8) {
        asm("mapa.shared::cluster.u32 %0, %1, %2;" : "=r"(dst_slot) : "r"(rs_local), "r"(lane));
        dst_slot += (uint32_t)(n * 8);
    }
    // Consumer poll address: this lane's two slots (m = 2*lane, 2*lane+1)
    const uint32_t poll_addr = rs_local + (uint32_t)(lane * 16);

    float* out_y = out;                            // [T,B,N]
    float* out_S = out + (size_t)TT * BB * NN;     // [T+1,B,N,D]

    // W_r row fragment: lane holds W_r[n][2*lane], W_r[n][2*lane+1]
    const float2 wrf = *(const float2*)(Wr + n * NN + 2 * lane);

    // Load S0 slice into registers, emit S[0]
    float4 s0_, s1_, s2_, s3_;
    {
        const float4* p = (const float4*)(S0 + (size_t)(b * NN + n) * DD + lane * 16);
        s0_ = p[0]; s1_ = p[1]; s2_ = p[2]; s3_ = p[3];
        float4* sp0 = (float4*)(out_S + (size_t)(b * NN + n) * DD + lane * 16);
        sp0[0] = s0_; sp0[1] = s1_; sp0[2] = s2_; sp0[3] = s3_;
    }

    const float* kp  = g_k + b * DD + lane * 16;
    const float* qp  = g_q + b * DD + lane * 16;
    const float* wxp = g_wx + b * NN + n;
    const float* alp = g_alpha + b * NN + n;
    float* yp = out_y + b * NN + n;
    float* sp = out_S + (size_t)((BB + b) * NN + n) * DD + lane * 16;  // S[1]

    // Prologue operands: k_0 current, kn = k_1
    float4 k0 = *(const float4*)(kp);      float4 k1 = *(const float4*)(kp + 4);
    float4 k2 = *(const float4*)(kp + 8);  float4 k3 = *(const float4*)(kp + 12);
    float4 q0 = *(const float4*)(qp);      float4 q1 = *(const float4*)(qp + 4);
    float4 q2 = *(const float4*)(qp + 8);  float4 q3 = *(const float4*)(qp + 12);
    float4 kn0 = *(const float4*)(kp + BB * DD);      float4 kn1 = *(const float4*)(kp + BB * DD + 4);
    float4 kn2 = *(const float4*)(kp + BB * DD + 8);  float4 kn3 = *(const float4*)(kp + BB * DD + 12);
    float wxv = __ldg(wxp);
    float alv = __ldg(alp);

    // r_0 = tanh(S0 . k_0); push (stamp 1, buf 0)
    {
        float sk = dot4(s0_, k0) + dot4(s1_, k1) + dot4(s2_, k2) + dot4(s3_, k3);
        float rv = fast_tanh(warp_sum(sk));
        if (lane < 8) {
            uint64_t pkt = ((uint64_t)1u << 32) | (uint64_t)__float_as_uint(rv);
            asm volatile("st.shared::cluster.b64 [%0], %1;" :: "r"(dst_slot), "l"(pkt) : "memory");
        }
    }

    for (int t = 0; t < TT; t++) {
        const int ib = t & 1;
        const uint32_t want = (uint32_t)(t + 1);

        // ---- Gap work (overlaps push transit from all CTAs) ----
        float A  = dot4(s0_, kn0) + dot4(s1_, kn1) + dot4(s2_, kn2) + dot4(s3_, kn3); // S.k_{t+1}
        float Bq = dot4(k0, kn0)  + dot4(k1, kn1)  + dot4(k2, kn2)  + dot4(k3, kn3);  // k_t.k_{t+1}
        float C  = dot4(s0_, q0)  + dot4(s1_, q1)  + dot4(s2_, q2)  + dot4(s3_, q3);  // S.q_t
        float Dq = dot4(k0, q0)   + dot4(k1, q1)   + dot4(k2, q2)   + dot4(k3, q3);   // k_t.q_t
        A = warp_sum(A); Bq = warp_sum(Bq); C = warp_sum(C); Dq = warp_sum(Dq);

        // Prefetch t+2 k, t+1 q/wx/alpha
        const int adv2 = (t < TT - 2) ? 2 * BB * DD : (TT - 1 - t) * BB * DD;
        const int advq = (t < TT - 1) ? BB * DD : 0;
        const int advn = (t < TT - 1) ? BB * NN : 0;
        float4 nk0 = *(const float4*)(kp + adv2);      float4 nk1 = *(const float4*)(kp + adv2 + 4);
        float4 nk2 = *(const float4*)(kp + adv2 + 8);  float4 nk3 = *(const float4*)(kp + adv2 + 12);
        float4 nq0 = *(const float4*)(qp + advq);      float4 nq1 = *(const float4*)(qp + advq + 4);
        float4 nq2 = *(const float4*)(qp + advq + 8);  float4 nq3 = *(const float4*)(qp + advq + 12);
        float nwx = __ldg(wxp + advn);
        float nal = __ldg(alp + advn);

        // ---- Poll this lane's two slots until both carry stamp t+1 ----
        float rm0, rm1;
        {
            uint32_t v0, st0, v1, st1;
            const uint32_t pa = poll_addr + (uint32_t)(ib * (NN * 8));
            do {
                asm volatile("ld.volatile.shared.v4.b32 {%0,%1,%2,%3}, [%4];"
                             : "=r"(v0), "=r"(st0), "=r"(v1), "=r"(st1) : "r"(pa));
            } while (st0 != want || st1 != want);
            rm0 = __uint_as_float(v0);
            rm1 = __uint_as_float(v1);
        }

        // v = tanh(W_r r + wx); c2 = (1-al)*v
        float pv = warp_sum(fmaf(wrf.x, rm0, wrf.y * rm1));
        float v  = fast_tanh(pv + wxv);
        const float al = alv;
        const float c2 = (1.0f - al) * v;

        // Next r (telescoped) and immediate push — shortest inter-CTA chain
        if (t < TT - 1) {
            float rv = fast_tanh(fmaf(al, A, c2 * Bq));
            if (lane < 8) {
                uint64_t pkt = ((uint64_t)(want + 1) << 32) | (uint64_t)__float_as_uint(rv);
                asm volatile("st.shared::cluster.b64 [%0], %1;"
                             :: "r"(dst_slot + (uint32_t)((1 - ib) * (NN * 8))), "l"(pkt) : "memory");
            }
        }

        // y_t (telescoped, off critical path)
        if (lane == 0) *yp = fast_tanh(fmaf(al, C, c2 * Dq));

        // S_t = al*S + c2*k ; stream to gmem
        UPD4(s0_, k0); UPD4(s1_, k1); UPD4(s2_, k2); UPD4(s3_, k3);
        __stcs((float4*)sp + 0, s0_);
        __stcs((float4*)sp + 1, s1_);
        __stcs((float4*)sp + 2, s2_);
        __stcs((float4*)sp + 3, s3_);

        // rotate operands
        k0 = kn0; k1 = kn1; k2 = kn2; k3 = kn3;
        kn0 = nk0; kn1 = nk1; kn2 = nk2; kn3 = nk3;
        q0 = nq0; q1 = nq1; q2 = nq2; q3 = nq3;
        wxv = nwx; alv = nal;
        kp += BB * DD; qp += BB * DD; wxp += BB * NN; alp += BB * NN;
        yp += BB * NN; sp += (size_t)BB * NN * DD;
    }
    // keep cluster alive until everyone is done reading peers' SMEM
    asm volatile("barrier.cluster.arrive.aligned;" ::: "memory");
    asm volatile("barrier.cluster.wait.aligned;"   ::: "memory");
}

// ============================================================================
// Launch
//   inputs: x, S0, W_k, W_q, W_x, W_r, b, W_alpha, b_alpha
//   output: concat( y[T,B,N], S[T+1,B,N,D] )  fp32
// ============================================================================
extern "C" void kernel_launch(void* const* d_in, const int* in_sizes, int n_in,
                              void* d_out, int out_size)
{
    const float* x   = (const float*)d_in[0];
    const float* S0  = (const float*)d_in[1];
    const float* Wk  = (const float*)d_in[2];
    const float* Wq  = (const float*)d_in[3];
    const float* Wx  = (const float*)d_in[4];
    const float* Wr  = (const float*)d_in[5];
    const float* bv  = (const float*)d_in[6];
    const float* Wa  = (const float*)d_in[7];
    const float* ba  = (const float*)d_in[8];
    float* out = (float*)d_out;

    dim3 pg(PM / TBM, PN / TBN);   // (32, 9)
    proj_kernel<<<pg, 256>>>(x, Wk, Wq, Wx, Wa, bv, ba);

    recur_kernel<<<64, 256>>>(S0, Wr, out);   // 8 clusters x 8 CTAs
}